// round 1
// baseline (speedup 1.0000x reference)
#include <cuda_runtime.h>
#include <cstdint>

// MQCCLayer: per-sample L2 normalize -> depthwise conv with F=2 shared
// unit-norm 3x3 filters -> de-normalize -> slice to 8 channels.
// Normalization cancels (conv is linear), slice is a no-op (C*F==8).
// => pure depthwise 3x3 conv: out[b, c*2+f, h, w] = sum_ij x[b,c,h+i-1,w+j-1]*W[f,i,j]
//    with W[f] = angles[f] / ||angles[f]||_2.

#define NB 32
#define NC 4
#define NH 512
#define NW 512
#define BROWS 8          // output rows per block
#define SPAD 4           // front pad (floats) so col x lives at smem idx x+4
#define SROW (SPAD + NW + 4)   // 520 floats per smem row

__device__ float g_w[18];   // normalized weights: [f][3][3], f in {0,1}

__global__ void mqcc_prep(const float* __restrict__ angles) {
    int f = threadIdx.x;
    if (f < 2) {
        float v[9];
        float s = 0.f;
#pragma unroll
        for (int i = 0; i < 9; i++) { v[i] = angles[f * 9 + i]; s += v[i] * v[i]; }
        float inv = rsqrtf(s);
        // one Newton-Raphson step to tighten MUFU.RSQ
        inv = inv * (1.5f - 0.5f * s * inv * inv);
#pragma unroll
        for (int i = 0; i < 9; i++) g_w[f * 9 + i] = v[i] * inv;
    }
}

__device__ __forceinline__ uint64_t packf2(float lo, float hi) {
    uint64_t r;
    asm("mov.b64 %0, {%1, %2};"
        : "=l"(r)
        : "r"(__float_as_uint(lo)), "r"(__float_as_uint(hi)));
    return r;
}

__device__ __forceinline__ uint64_t fma2(uint64_t a, uint64_t b, uint64_t c) {
    uint64_t d;
    asm("fma.rn.f32x2 %0, %1, %2, %3;" : "=l"(d) : "l"(a), "l"(b), "l"(c));
    return d;
}

__global__ void __launch_bounds__(128, 1)
mqcc_conv(const float* __restrict__ x, float* __restrict__ out) {
    __shared__ float sm[(BROWS + 2) * SROW];
    const int t = threadIdx.x;
    const int bc = blockIdx.y;                 // b*NC + c
    const int r0 = blockIdx.x * BROWS;         // first output row of this block
    const float* __restrict__ xin = x + (size_t)bc * (NH * NW);

    // Cooperative load of BROWS+2 input rows into padded SMEM.
    // smem idx = col + SPAD; idx[0..3] and idx[516..519] are zero halo.
#pragma unroll
    for (int i = 0; i < BROWS + 2; i++) {
        int gr = r0 - 1 + i;
        float4 v = make_float4(0.f, 0.f, 0.f, 0.f);
        if ((unsigned)gr < (unsigned)NH)
            v = *reinterpret_cast<const float4*>(xin + (size_t)gr * NW + 4 * t);
        *reinterpret_cast<float4*>(&sm[i * SROW + SPAD + 4 * t]) = v;
        if (t < 2) {
            float4 z = make_float4(0.f, 0.f, 0.f, 0.f);
            // t==0 zeros idx 0..3 (left halo), t==1 zeros idx 516..519 (right halo)
            *reinterpret_cast<float4*>(&sm[i * SROW + t * (SPAD + NW)]) = z;
        }
    }
    __syncthreads();

    // Broadcast-packed weights: wq[f*9 + i] = (w, w) as f32x2
    uint64_t wq[18];
#pragma unroll
    for (int i = 0; i < 18; i++) { float w = g_w[i]; wq[i] = packf2(w, w); }

    // Sliding window of pre-packed column pairs. For this thread's 4 output
    // cols c0=4t .. c0+3, per input row we need cols c0-1..c0+4, packed as
    // p[k] = (v[c0-1+k], v[c0+k]) for k=0..4.
    uint64_t P[3][5];
    auto load_row = [&](int i, uint64_t* p) {
        const float* s = &sm[i * SROW + SPAD + 4 * t];
        float4 M = *reinterpret_cast<const float4*>(s);
        float l = s[-1];
        float r = s[4];
        p[0] = packf2(l, M.x);
        p[1] = packf2(M.x, M.y);
        p[2] = packf2(M.y, M.z);
        p[3] = packf2(M.z, M.w);
        p[4] = packf2(M.w, r);
    };
    load_row(0, P[0]);
    load_row(1, P[1]);

    const int b = bc >> 2, c = bc & 3;
    float* __restrict__ o0 =
        out + ((size_t)(b * 8 + c * 2) * NH + r0) * NW + 4 * t;
    float* __restrict__ o1 = o0 + (size_t)NH * NW;

#pragma unroll
    for (int r = 0; r < BROWS; r++) {
        load_row(r + 2, P[(r + 2) % 3]);
        // acc pairs: a0 = filter0 cols(0,1), a1 = filter0 cols(2,3),
        //            a2 = filter1 cols(0,1), a3 = filter1 cols(2,3)
        uint64_t a0 = 0, a1 = 0, a2 = 0, a3 = 0;
#pragma unroll
        for (int ir = 0; ir < 3; ir++) {
            const uint64_t* p = P[(r + ir) % 3];
            const uint64_t* w0 = &wq[ir * 3];
            const uint64_t* w1 = &wq[9 + ir * 3];
#pragma unroll
            for (int j = 0; j < 3; j++) {
                a0 = fma2(w0[j], p[j], a0);
                a1 = fma2(w0[j], p[j + 2], a1);
                a2 = fma2(w1[j], p[j], a2);
                a3 = fma2(w1[j], p[j + 2], a3);
            }
        }
        ulonglong2 s0; s0.x = a0; s0.y = a1;
        ulonglong2 s1; s1.x = a2; s1.y = a3;
        *reinterpret_cast<ulonglong2*>(o0) = s0;   // channel c*2+0
        *reinterpret_cast<ulonglong2*>(o1) = s1;   // channel c*2+1
        o0 += NW;
        o1 += NW;
    }
}

extern "C" void kernel_launch(void* const* d_in, const int* in_sizes, int n_in,
                              void* d_out, int out_size) {
    const float* x = (const float*)d_in[0];        // (32, 4, 512, 512) f32
    const float* angles = (const float*)d_in[1];   // (2, 3, 3) f32
    float* out = (float*)d_out;                    // (32, 8, 512, 512) f32

    mqcc_prep<<<1, 32>>>(angles);
    dim3 grid(NH / BROWS, NB * NC);
    mqcc_conv<<<grid, 128>>>(x, out);
}

// round 2
// speedup vs baseline: 1.0259x; 1.0259x over previous
#include <cuda_runtime.h>
#include <cstdint>

// MQCCLayer == depthwise 3x3 conv with F=2 shared unit-norm filters.
// The per-sample L2 normalize / de-normalize cancels (conv is linear);
// the channel slice is a no-op (C*F == OUT_CHANNELS == 8).
// out[b, c*2+f, h, w] = sum_ij x[b,c,h+i-1,w+j-1] * W[f,i,j],
// W[f] = angles[f]/||angles[f]||.
//
// Single kernel: weight normalization is recomputed per-thread (18 cached
// loads + 2 rsqrt) to avoid a second launch. Scalar FFMA (no f32x2 packing)
// to keep regs <= 64 -> 8 blocks/SM -> enough warps to saturate HBM.

#define NB 32
#define NC 4
#define NH 512
#define NW 512
#define BROWS 8              // output rows per block
#define SPAD 4               // front pad so col x lives at smem idx x+SPAD
#define SROW (SPAD + NW + 4) // 520 floats per smem row

__global__ void __launch_bounds__(128, 8)
mqcc_conv(const float* __restrict__ x, const float* __restrict__ angles,
          float* __restrict__ out) {
    __shared__ float sm[(BROWS + 2) * SROW];
    const int t = threadIdx.x;
    const int bc = blockIdx.y;              // b*NC + c
    const int r0 = blockIdx.x * BROWS;      // first output row of this block
    const float* __restrict__ xin = x + (size_t)bc * (NH * NW);

    // Stage BROWS+2 input rows into padded SMEM (128 thr x float4 = 512 cols).
#pragma unroll
    for (int i = 0; i < BROWS + 2; i++) {
        int gr = r0 - 1 + i;
        float4 v = make_float4(0.f, 0.f, 0.f, 0.f);
        if ((unsigned)gr < (unsigned)NH)
            v = *reinterpret_cast<const float4*>(xin + (size_t)gr * NW + 4 * t);
        *reinterpret_cast<float4*>(&sm[i * SROW + SPAD + 4 * t]) = v;
    }
    // Zero halos: 10 rows x {left idx 0..3, right idx 516..519}
    if (t < 2 * (BROWS + 2)) {
        int i = t >> 1, side = t & 1;
        *reinterpret_cast<float4*>(&sm[i * SROW + side * (SPAD + NW)]) =
            make_float4(0.f, 0.f, 0.f, 0.f);
    }

    // Normalized weights, computed redundantly per thread (L2-cached loads).
    float w[18];
#pragma unroll
    for (int f = 0; f < 2; f++) {
        float s = 0.f;
#pragma unroll
        for (int i = 0; i < 9; i++) {
            float v = __ldg(&angles[f * 9 + i]);
            w[f * 9 + i] = v;
            s += v * v;
        }
        float inv = rsqrtf(s);
        inv = inv * (1.5f - 0.5f * s * inv * inv);   // NR step
#pragma unroll
        for (int i = 0; i < 9; i++) w[f * 9 + i] *= inv;
    }
    __syncthreads();

    // Sliding 3-row window of 6 input cols (c0-1 .. c0+4), c0 = 4t.
    float W[3][6];
    auto load_row = [&](int i, float* d) {
        const float* s = &sm[i * SROW + SPAD + 4 * t];
        float4 M = *reinterpret_cast<const float4*>(s);
        d[0] = s[-1];
        d[1] = M.x; d[2] = M.y; d[3] = M.z; d[4] = M.w;
        d[5] = s[4];
    };
    load_row(0, W[0]);
    load_row(1, W[1]);

    const int b = bc >> 2, c = bc & 3;
    float* __restrict__ o0 =
        out + ((size_t)(b * 8 + c * 2) * NH + r0) * NW + 4 * t;
    float* __restrict__ o1 = o0 + (size_t)NH * NW;

#pragma unroll
    for (int r = 0; r < BROWS; r++) {
        load_row(r + 2, W[(r + 2) % 3]);
        float a0 = 0.f, a1 = 0.f, a2 = 0.f, a3 = 0.f;   // filter 0, cols 0..3
        float b0 = 0.f, b1 = 0.f, b2 = 0.f, b3 = 0.f;   // filter 1, cols 0..3
#pragma unroll
        for (int ir = 0; ir < 3; ir++) {
            const float* Wr = W[(r + ir) % 3];
            const float* w0 = &w[ir * 3];
            const float* w1 = &w[9 + ir * 3];
#pragma unroll
            for (int j = 0; j < 3; j++) {
                float f0 = w0[j], f1 = w1[j];
                a0 = fmaf(f0, Wr[j + 0], a0);
                a1 = fmaf(f0, Wr[j + 1], a1);
                a2 = fmaf(f0, Wr[j + 2], a2);
                a3 = fmaf(f0, Wr[j + 3], a3);
                b0 = fmaf(f1, Wr[j + 0], b0);
                b1 = fmaf(f1, Wr[j + 1], b1);
                b2 = fmaf(f1, Wr[j + 2], b2);
                b3 = fmaf(f1, Wr[j + 3], b3);
            }
        }
        *reinterpret_cast<float4*>(o0) = make_float4(a0, a1, a2, a3);
        *reinterpret_cast<float4*>(o1) = make_float4(b0, b1, b2, b3);
        o0 += NW;
        o1 += NW;
    }
}

extern "C" void kernel_launch(void* const* d_in, const int* in_sizes, int n_in,
                              void* d_out, int out_size) {
    const float* x = (const float*)d_in[0];        // (32, 4, 512, 512) f32
    const float* angles = (const float*)d_in[1];   // (2, 3, 3) f32
    float* out = (float*)d_out;                    // (32, 8, 512, 512) f32

    dim3 grid(NH / BROWS, NB * NC);
    mqcc_conv<<<grid, 128>>>(x, angles, out);
}